// round 9
// baseline (speedup 1.0000x reference)
#include <cuda_runtime.h>
#include <cstdint>

#define HID   100
#define GROWS 400
#define TENC  4096
#define TDEC  4096
#define NCLS  6
#define NTH   256          // 8 warps: threads 0-199 matvec (pair per hidden unit), warp 7 logits
#define LOG2E 1.4426950408889634f

typedef unsigned long long ull;

// precomputed input contributions, packed [t][j][4] = (i,f,g,o) of hidden unit j
__device__ float g_gge[TENC * GROWS];   // encoder
__device__ float g_ggd[TDEC * GROWS];   // decoder

// ---- packed f32x2 helpers ----
__device__ __forceinline__ ull fma2(ull a, ull b, ull c) {
    ull d;
    asm("fma.rn.f32x2 %0, %1, %2, %3;" : "=l"(d) : "l"(a), "l"(b), "l"(c));
    return d;
}
__device__ __forceinline__ float ex2f(float x) {
    float y; asm("ex2.approx.f32 %0, %1;" : "=f"(y) : "f"(x)); return y;
}
__device__ __forceinline__ float rcpf(float x) {
    float y; asm("rcp.approx.f32 %0, %1;" : "=f"(y) : "f"(x)); return y;
}
__device__ __forceinline__ float sigf(float x) {
    return rcpf(1.0f + ex2f(-LOG2E * x));
}
__device__ __forceinline__ float tanhf_fast(float x) {
    return 1.0f - 2.0f * rcpf(1.0f + ex2f((2.0f * LOG2E) * x));
}
__device__ __forceinline__ float hsum2(ull s) {
    float lo, hi;
    asm("mov.b64 {%0,%1},%2;" : "=f"(lo), "=f"(hi) : "l"(s));
    return lo + hi;
}

// ---------------- prep kernel: gx precompute (fully parallel) ----------------
__global__ void gx_prep_kernel(const float* __restrict__ x,     // [TENC,3]
                               const int*   __restrict__ y,     // [TDEC]
                               const float* __restrict__ eWih,  // [400,3]
                               const float* __restrict__ ebih,
                               const float* __restrict__ ebhh,
                               const float* __restrict__ dWih,  // [400,1]
                               const float* __restrict__ dbih,
                               const float* __restrict__ dbhh)
{
    int idx = blockIdx.x * blockDim.x + threadIdx.x;
    if (idx >= TENC * GROWS) return;
    int t = idx / GROWS;
    int r = idx - t * GROWS;
    int j = r % 100, gate = r / 100;          // gate: 0=i,1=f,2=g,3=o
    int dst = t * GROWS + j * 4 + gate;
    g_gge[dst] = ebih[r] + ebhh[r]
               + x[3*t+0] * eWih[3*r+0]
               + x[3*t+1] * eWih[3*r+1]
               + x[3*t+2] * eWih[3*r+2];
    g_ggd[dst] = dbih[r] + dbhh[r] + (float)y[t] * dWih[r];
}

// load this thread's weight slice: 4 gate rows of unit j, cols [half*52, half*52+52)
__device__ __forceinline__ void load_w(ull (&w)[104], const float* __restrict__ Whh,
                                       int j, int half) {
#pragma unroll
    for (int g = 0; g < 4; ++g) {
        const int row = j + g * 100;
        const ull* wr = (const ull*)(Whh + row * HID + half * 52);
        if (half == 0) {
#pragma unroll
            for (int k = 0; k < 26; ++k) w[g * 26 + k] = wr[k];
        } else {
#pragma unroll
            for (int k = 0; k < 24; ++k) w[g * 26 + k] = wr[k];
            w[g * 26 + 24] = 0ull;
            w[g * 26 + 25] = 0ull;           // pad cols 100..103
        }
    }
}

// One recurrence phase (encoder or decoder), fully inlined.
template<bool DEC>
__device__ __forceinline__ void run_phase(
    int T, const float* __restrict__ gg,
    ull (&w)[104], float& c, int& p,
    float (&hbuf)[2][128],
    const float* slw, const float* slb, float* __restrict__ out,
    int tid, unsigned mvmask)
{
    const bool mv   = (tid < 200);
    const int  j    = tid >> 1;
    const int  half = tid & 1;
    const bool lwrp = ((tid >> 5) == 7);      // logits warp (threads 224-255)
    const int lane  = tid & 31;
    const int cls   = lane & 7;
    const int piece = lane >> 3;              // 4 pieces of 25

    // gx for step 0 (even threads only)
    float4 gx = make_float4(0.f, 0.f, 0.f, 0.f);
    if (mv && half == 0) gx = __ldg(((const float4*)gg) + j);

#pragma unroll 1
    for (int s = 0; s < T; ++s) {
        const bool work = (!DEC) || (s < T - 1);
        if (mv && work) {
            // prefetch next step's gx (even threads; hidden under the matvec)
            float4 nx = gx;
            if (half == 0) {
                const int sn = s + 1;
                const bool nvalid = DEC ? (sn < T - 1) : (sn < T);
                if (nvalid) nx = __ldg(((const float4*)(gg + sn * GROWS)) + j);
            }

            // 4 partial dots over this thread's 52-column half of h
            const ulonglong2* hp =
                (const ulonglong2*)((const float*)hbuf[p] + half * 52);
            ull a0 = 0ull, a1 = 0ull, a2 = 0ull, a3 = 0ull;
#pragma unroll
            for (int k = 0; k < 13; ++k) {
                const ulonglong2 hv = hp[k];
                a0 = fma2(w[      2*k], hv.x, a0); a0 = fma2(w[      2*k+1], hv.y, a0);
                a1 = fma2(w[ 26 + 2*k], hv.x, a1); a1 = fma2(w[ 26 + 2*k+1], hv.y, a1);
                a2 = fma2(w[ 52 + 2*k], hv.x, a2); a2 = fma2(w[ 52 + 2*k+1], hv.y, a2);
                a3 = fma2(w[ 78 + 2*k], hv.x, a3); a3 = fma2(w[ 78 + 2*k+1], hv.y, a3);
            }
            float s0 = hsum2(a0), s1 = hsum2(a1), s2 = hsum2(a2), s3 = hsum2(a3);
            if (half == 0) { s0 += gx.x; s1 += gx.y; s2 += gx.z; s3 += gx.w; }
            // symmetric exchange: both threads of the pair get all 4 full sums
            const float r0 = s0 + __shfl_xor_sync(mvmask, s0, 1);
            const float r1 = s1 + __shfl_xor_sync(mvmask, s1, 1);
            const float r2 = s2 + __shfl_xor_sync(mvmask, s2, 1);
            const float r3 = s3 + __shfl_xor_sync(mvmask, s3, 1);
            // both compute the update redundantly (identical, divergence-free)
            const float iv = sigf(r0);
            const float fv = sigf(r1);
            const float gv = tanhf_fast(r2);
            const float ov = sigf(r3);
            c = fmaf(fv, c, iv * gv);
            const float h = ov * tanhf_fast(c);
            if (half == 0) hbuf[p ^ 1][j] = h;
            gx = nx;
        }
        if (DEC && lwrp && s >= 1) {
            // logits of step s-1 from hbuf[p] = h_{s-1}, overlapped with matvec
            float acc = 0.0f;
            const float* lp = slw + cls * HID + piece * 25;    // cls 6,7 hit zero pad
            const float* hq = &hbuf[p][piece * 25];
#pragma unroll
            for (int k = 0; k < 25; ++k)
                acc = fmaf(lp[k], hq[k], acc);
            acc += __shfl_xor_sync(0xffffffffu, acc, 8);
            acc += __shfl_xor_sync(0xffffffffu, acc, 16);
            if (piece == 0 && cls < NCLS)
                out[(s - 1) * NCLS + cls] = acc + slb[cls];
        }
        __syncthreads();   // single barrier: h_{p^1} complete, hbuf[p] readers done
        if (work) p ^= 1;
    }
}

// ---------------- persistent recurrence kernel ----------------
__global__ void __launch_bounds__(NTH, 1)
lstm_encdec_kernel(const float* __restrict__ eWhh,   // [400,100]
                   const float* __restrict__ dWhh,   // [400,100]
                   const float* __restrict__ linW,   // [6,100]
                   const float* __restrict__ linb,   // [6]
                   float* __restrict__ out)          // [TDEC,6]
{
    __shared__ __align__(1024) float hbuf[2][128];   // h padded to 104 (pad = 0)
    __shared__ float slw[8 * HID];                   // lin_W padded to 8 rows
    __shared__ float slb[NCLS];

    const int tid = threadIdx.x;

    // ---- init (zero FULL padded h rows: cols 100..103 are read by odd threads) ----
    if (tid < 128) { hbuf[0][tid] = 0.0f; hbuf[1][tid] = 0.0f; }
    if (tid < NCLS) { out[(TDEC - 1) * NCLS + tid] = 0.0f; slb[tid] = linb[tid]; }
    for (int i = tid; i < 8 * HID; i += NTH)
        slw[i] = (i < NCLS * HID) ? linW[i] : 0.0f;
    float c = 0.0f;                                  // both threads of pair keep c[j]

    const int j    = tid >> 1;
    const int half = tid & 1;
    const unsigned mvmask = (tid >= 192) ? 0xFFu : 0xFFFFFFFFu;

    // ---- encoder weights: 4 gate rows x 26 f32x2 (208 regs) ----
    ull w[104];
    if (tid < 200) load_w(w, eWhh, j, half);
    __syncthreads();

    int p = 0;

    // ================= encoder =================
    run_phase<false>(TENC, g_gge, w, c, p, hbuf, slw, slb, out, tid, mvmask);

    // ---- decoder weights (one-time reload, registers only) ----
    if (tid < 200) load_w(w, dWhh, j, half);

    // ================= decoder =================
    run_phase<true>(TDEC, g_ggd, w, c, p, hbuf, slw, slb, out, tid, mvmask);
}

extern "C" void kernel_launch(void* const* d_in, const int* in_sizes, int n_in,
                              void* d_out, int out_size) {
    const float* x     = (const float*)d_in[0];
    const int*   y     = (const int*)  d_in[1];
    const float* eWih  = (const float*)d_in[2];
    const float* eWhh  = (const float*)d_in[3];
    const float* ebih  = (const float*)d_in[4];
    const float* ebhh  = (const float*)d_in[5];
    const float* dWih  = (const float*)d_in[6];
    const float* dWhh  = (const float*)d_in[7];
    const float* dbih  = (const float*)d_in[8];
    const float* dbhh  = (const float*)d_in[9];
    const float* linW  = (const float*)d_in[10];
    const float* linb  = (const float*)d_in[11];
    float* out = (float*)d_out;

    const int n = TENC * GROWS;
    gx_prep_kernel<<<(n + 255) / 256, 256>>>(x, y, eWih, ebih, ebhh,
                                             dWih, dbih, dbhh);
    lstm_encdec_kernel<<<1, NTH>>>(eWhh, dWhh, linW, linb, out);
}

// round 10
// speedup vs baseline: 1.1641x; 1.1641x over previous
#include <cuda_runtime.h>
#include <cstdint>

#define HID   100
#define GROWS 400
#define TENC  4096
#define TDEC  4096
#define NCLS  6
#define NTH   256          // 8 warps: threads 0-199 matvec (2 rows each), warp 7 logits
#define LOG2E 1.4426950408889634f

typedef unsigned long long ull;

// precomputed input contributions, packed per-thread:
// thread t (j=t>>1): slot0 = row (j + (t&1)*100)  [i or f]
//                    slot1 = row (j + (t&1)*100 + 200) [g or o]
__device__ float g_gge[TENC * GROWS];   // encoder
__device__ float g_ggd[TDEC * GROWS];   // decoder

// ---- packed f32x2 helpers ----
__device__ __forceinline__ ull fma2(ull a, ull b, ull c) {
    ull d;
    asm("fma.rn.f32x2 %0, %1, %2, %3;" : "=l"(d) : "l"(a), "l"(b), "l"(c));
    return d;
}
__device__ __forceinline__ ull add2(ull a, ull b) {
    ull d;
    asm("add.rn.f32x2 %0, %1, %2;" : "=l"(d) : "l"(a), "l"(b));
    return d;
}
__device__ __forceinline__ float ex2f(float x) {
    float y; asm("ex2.approx.f32 %0, %1;" : "=f"(y) : "f"(x)); return y;
}
__device__ __forceinline__ float rcpf(float x) {
    float y; asm("rcp.approx.f32 %0, %1;" : "=f"(y) : "f"(x)); return y;
}
__device__ __forceinline__ float sigf(float x) {
    return rcpf(1.0f + ex2f(-LOG2E * x));
}
__device__ __forceinline__ float tanhf_fast(float x) {
    return 1.0f - 2.0f * rcpf(1.0f + ex2f((2.0f * LOG2E) * x));
}

// Two dots sharing each h load (4 FFMA2 per LDS.128), 4-deep pipelined.
__device__ __forceinline__ void dotpair(const ull (&w1)[50], const ull (&w2)[50],
                                        unsigned hb, float gx1, float gx2,
                                        float& d1, float& d2) {
    ull bxa[4], bya[4];
#pragma unroll
    for (int m = 0; m < 4; ++m)
        asm volatile("ld.shared.v2.b64 {%0,%1},[%2];"
                     : "=l"(bxa[m]), "=l"(bya[m]) : "r"(hb + 16u * m));
    ull p0, p1 = 0ull, q0, q1 = 0ull;
    asm("mov.b64 %0,{%1,%2};" : "=l"(p0) : "f"(gx1), "f"(0.0f));
    asm("mov.b64 %0,{%1,%2};" : "=l"(q0) : "f"(gx2), "f"(0.0f));
#pragma unroll
    for (int m = 0; m < 25; ++m) {
        const int sl = m & 3;
        p0 = fma2(w1[2*m],     bxa[sl], p0);
        p1 = fma2(w1[2*m + 1], bya[sl], p1);
        q0 = fma2(w2[2*m],     bxa[sl], q0);
        q1 = fma2(w2[2*m + 1], bya[sl], q1);
        if (m + 4 < 25)
            asm volatile("ld.shared.v2.b64 {%0,%1},[%2];"
                         : "=l"(bxa[sl]), "=l"(bya[sl]) : "r"(hb + 16u * (m + 4)));
    }
    ull s1 = add2(p0, p1), s2 = add2(q0, q1);
    float a, b, e, f;
    asm("mov.b64 {%0,%1},%2;" : "=f"(a), "=f"(b) : "l"(s1));
    asm("mov.b64 {%0,%1},%2;" : "=f"(e), "=f"(f) : "l"(s2));
    d1 = a + b;
    d2 = e + f;
}

// ---------------- prep kernel: gx precompute (fully parallel) ----------------
__global__ void gx_prep_kernel(const float* __restrict__ x,     // [TENC,3]
                               const int*   __restrict__ y,     // [TDEC]
                               const float* __restrict__ eWih,  // [400,3]
                               const float* __restrict__ ebih,
                               const float* __restrict__ ebhh,
                               const float* __restrict__ dWih,  // [400,1]
                               const float* __restrict__ dbih,
                               const float* __restrict__ dbhh)
{
    int idx = blockIdx.x * blockDim.x + threadIdx.x;
    if (idx >= TENC * GROWS) return;
    int t = idx / GROWS;
    int r = idx - t * GROWS;
    int rm = r % 100, blk = r / 100;
    int thr  = 2 * rm + (blk & 1);
    int slot = blk >> 1;
    int dst = t * GROWS + thr * 2 + slot;
    g_gge[dst] = ebih[r] + ebhh[r]
               + x[3*t+0] * eWih[3*r+0]
               + x[3*t+1] * eWih[3*r+1]
               + x[3*t+2] * eWih[3*r+2];
    g_ggd[dst] = dbih[r] + dbhh[r] + (float)y[t] * dWih[r];
}

// One LSTM step for the matvec threads. Branchless clamped prefetch.
__device__ __forceinline__ void lstm_body(
    const float* __restrict__ gg, int s, int T,
    const ull (&w1)[50], const ull (&w2)[50],
    unsigned hbRead, float* __restrict__ hWrite,
    float2& gx, float& c,
    int tid, int j, bool ev, unsigned mvmask,
    float aa2, float bb2, float kk2)
{
    int sn = s + 1; if (sn > T - 1) sn = T - 1;           // clamp, no branch body
    const float2 nx = __ldg(((const float2*)(gg + sn * GROWS)) + tid);
    float d1, d2;
    dotpair(w1, w2, hbRead, gx.x, gx.y, d1, d2);
    // slot0: i (even) or f (odd) -> sigmoid
    const float act1 = sigf(d1);
    // slot1: g (even, tanh) or o (odd, sigmoid)
    const float act2 = fmaf(bb2, rcpf(1.0f + ex2f(kk2 * d2)), aa2);
    const float pf = __shfl_xor_sync(mvmask, act1, 1);
    const float po = __shfl_xor_sync(mvmask, act2, 1);
    if (ev) {
        c = fmaf(pf, c, act1 * act2);                     // c = f*c + i*g
        hWrite[j] = po * tanhf_fast(c);                   // h = o*tanh(c)
    }
    gx = nx;
}

// Logits of one decoder step (warp 7 only). hRead = h of that step.
__device__ __forceinline__ void logits_body(
    const float* __restrict__ hRead,
    const float* __restrict__ slw, const float* __restrict__ slb,
    float* __restrict__ out, int orow, int cls, int piece)
{
    float acc = 0.0f;
    const float* lp = slw + cls * HID + piece * 25;       // cls 6,7 hit zero pad
    const float* hq = hRead + piece * 25;
#pragma unroll
    for (int k = 0; k < 25; ++k)
        acc = fmaf(lp[k], hq[k], acc);
    acc += __shfl_xor_sync(0xffffffffu, acc, 8);
    acc += __shfl_xor_sync(0xffffffffu, acc, 16);
    if (piece == 0 && cls < NCLS)
        out[orow * NCLS + cls] = acc + slb[cls];
}

// ---------------- persistent recurrence kernel ----------------
__global__ void __launch_bounds__(NTH, 1)
lstm_encdec_kernel(const float* __restrict__ eWhh,   // [400,100]
                   const float* __restrict__ dWhh,   // [400,100]
                   const float* __restrict__ linW,   // [6,100]
                   const float* __restrict__ linb,   // [6]
                   float* __restrict__ out)          // [TDEC,6]
{
    __shared__ __align__(1024) float hbuf[2][128];
    __shared__ float slw[8 * HID];                   // lin_W padded to 8 rows
    __shared__ float slb[NCLS];

    const int tid = threadIdx.x;

    // ---- init ----
    if (tid < 128) { hbuf[0][tid] = 0.0f; hbuf[1][tid] = 0.0f; }
    if (tid < NCLS) { out[(TDEC - 1) * NCLS + tid] = 0.0f; slb[tid] = linb[tid]; }
    for (int i = tid; i < 8 * HID; i += NTH)
        slw[i] = (i < NCLS * HID) ? linW[i] : 0.0f;
    float c = 0.0f;                                  // even thread t owns c[t>>1]

    const bool mv   = (tid < 200);
    const bool lwrp = ((tid >> 5) == 7);
    const bool ev   = !(tid & 1);
    const int  j    = tid >> 1;
    const int lane  = tid & 31;
    const int cls   = lane & 7;
    const int piece = lane >> 3;
    const unsigned mvmask = (tid >= 192) ? 0xFFu : 0xFFFFFFFFu;

    // act2 constants: even -> tanh (g), odd -> sigmoid (o)
    const float aa2 = ev ? 1.0f : 0.0f;
    const float bb2 = ev ? -2.0f : 1.0f;
    const float kk2 = ev ? (2.0f * LOG2E) : (-LOG2E);

    // row indices: r1 = i/f row, r2 = g/o row
    const int r1 = j + (tid & 1) * 100;
    const int r2 = r1 + 200;

    // ---- encoder weights (200 regs) ----
    ull w1[50], w2[50];
    if (mv) {
        const ull* p1 = (const ull*)(eWhh + r1 * HID);
        const ull* p2 = (const ull*)(eWhh + r2 * HID);
#pragma unroll
        for (int k = 0; k < 50; ++k) { w1[k] = p1[k]; w2[k] = p2[k]; }
    }
    __syncthreads();

    const unsigned hb0 = (unsigned)__cvta_generic_to_shared(&hbuf[0][0]);
    const unsigned hb1 = hb0 + 512u;
    float* const h0 = &hbuf[0][0];
    float* const h1 = &hbuf[1][0];

    // gx for step 0
    float2 gx = make_float2(0.0f, 0.0f);
    if (mv) gx = __ldg(((const float2*)g_gge) + tid);

    // ================= encoder: 4096 steps, unrolled x2 =================
#pragma unroll 1
    for (int s = 0; s < TENC; s += 2) {
        if (mv) lstm_body(g_gge, s,     TENC, w1, w2, hb0, h1, gx, c,
                          tid, j, ev, mvmask, aa2, bb2, kk2);
        __syncthreads();
        if (mv) lstm_body(g_gge, s + 1, TENC, w1, w2, hb1, h0, gx, c,
                          tid, j, ev, mvmask, aa2, bb2, kk2);
        __syncthreads();
    }
    // h_enc in hbuf[0], c in registers

    // ---- decoder weights (registers only; prior barrier covers hbuf) ----
    if (mv) {
        const ull* p1 = (const ull*)(dWhh + r1 * HID);
        const ull* p2 = (const ull*)(dWhh + r2 * HID);
#pragma unroll
        for (int k = 0; k < 50; ++k) { w1[k] = p1[k]; w2[k] = p2[k]; }
        gx = __ldg(((const float2*)g_ggd) + tid);
    }

    // ================= decoder =================
    // Steps 0..4093 in an always-work unrolled loop; logits of step k are
    // produced by warp 7 one iteration later from the buffer the matvec reads.
#pragma unroll 1
    for (int s = 0; s < TDEC - 2; s += 2) {
        if (mv) {
            lstm_body(g_ggd, s, TDEC, w1, w2, hb0, h1, gx, c,
                      tid, j, ev, mvmask, aa2, bb2, kk2);
        } else if (lwrp && s >= 1) {
            logits_body(h0, slw, slb, out, s - 1, cls, piece);
        }
        __syncthreads();
        if (mv) {
            lstm_body(g_ggd, s + 1, TDEC, w1, w2, hb1, h0, gx, c,
                      tid, j, ev, mvmask, aa2, bb2, kk2);
        } else if (lwrp) {
            logits_body(h1, slw, slb, out, s, cls, piece);
        }
        __syncthreads();
    }
    // step 4094 (last work step): reads hbuf[0], writes hbuf[1];
    // logits of step 4093 from hbuf[0]
    if (mv) {
        lstm_body(g_ggd, TDEC - 2, TDEC, w1, w2, hb0, h1, gx, c,
                  tid, j, ev, mvmask, aa2, bb2, kk2);
    } else if (lwrp) {
        logits_body(h0, slw, slb, out, TDEC - 3, cls, piece);
    }
    __syncthreads();
    // logits of step 4094 from hbuf[1] (out row 4094; row 4095 stays zero)
    if (lwrp) logits_body(h1, slw, slb, out, TDEC - 2, cls, piece);
}

extern "C" void kernel_launch(void* const* d_in, const int* in_sizes, int n_in,
                              void* d_out, int out_size) {
    const float* x     = (const float*)d_in[0];
    const int*   y     = (const int*)  d_in[1];
    const float* eWih  = (const float*)d_in[2];
    const float* eWhh  = (const float*)d_in[3];
    const float* ebih  = (const float*)d_in[4];
    const float* ebhh  = (const float*)d_in[5];
    const float* dWih  = (const float*)d_in[6];
    const float* dWhh  = (const float*)d_in[7];
    const float* dbih  = (const float*)d_in[8];
    const float* dbhh  = (const float*)d_in[9];
    const float* linW  = (const float*)d_in[10];
    const float* linb  = (const float*)d_in[11];
    float* out = (float*)d_out;

    const int n = TENC * GROWS;
    gx_prep_kernel<<<(n + 255) / 256, 256>>>(x, y, eWih, ebih, ebhh,
                                             dWih, dbih, dbhh);
    lstm_encdec_kernel<<<1, NTH>>>(eWhh, dWhh, linW, linb, out);
}